// round 13
// baseline (speedup 1.0000x reference)
#include <cuda_runtime.h>
#include <cuda_fp16.h>
#include <cstdint>
#include <cstddef>

// Xonv2D: out[b,o,h,w] = sum_{c,kh,kw} x[b,c,h+kh-1,w+kw-1] * W[h,w,o,c,kh,kw] + bias[h,w,o]
// B=4, CIN=COUT=16, K=3, H=W=128. Weights = 151MB streamed once -> HBM-bound.
// Round 13 = Round 10 (best: 3 CTAs/SM x 256thr, 4px chunks, ring-2 TMA, fp16 x
// tile) + L2 PREFETCH of weight chunk j+4 each iteration. Prefetch has no buffer
// bound -> DRAM queues stay full; the ring-2 TMA then hits L2 instead of DRAM.

static constexpr int Hc = 128, Wc = 128;
static constexpr int GROUPS = 4096;                      // 4-pixel groups
static constexpr int FLOATS_PER_PX = 16 * 16 * 9;        // 2304
static constexpr int CHUNK_FLOATS  = 4 * FLOATS_PER_PX;  // 9216
static constexpr int CHUNK_BYTES   = CHUNK_FLOATS * 4;   // 36864
static constexpr int XTILE         = 1152;               // halfs (16c*3r*6w*4b)
static constexpr int SMEM_X_OFF    = 2 * CHUNK_BYTES;            // 73728
static constexpr int SMEM_MBAR_OFF = SMEM_X_OFF + XTILE * 2;     // 76032
static constexpr int SMEM_TOTAL    = SMEM_MBAR_OFF + 16;         // 76048 (x3 <= 233472)
static constexpr int GRID          = 456;                // 3 CTAs/SM * 152 SMs
static constexpr int NT            = 256;
static constexpr int PF_DIST       = 4;                  // prefetch distance (chunks)

__device__ __forceinline__ uint32_t smem_u32(const void* p) {
    return (uint32_t)__cvta_generic_to_shared(p);
}
__device__ __forceinline__ void mbar_init(uint32_t a, uint32_t count) {
    asm volatile("mbarrier.init.shared.b64 [%0], %1;" :: "r"(a), "r"(count) : "memory");
}
__device__ __forceinline__ void mbar_expect_tx(uint32_t a, uint32_t bytes) {
    asm volatile("mbarrier.arrive.expect_tx.shared.b64 _, [%0], %1;" :: "r"(a), "r"(bytes) : "memory");
}
__device__ __forceinline__ void tma_bulk_g2s(uint32_t dst, const void* src, uint32_t bytes, uint32_t mbar) {
    asm volatile("cp.async.bulk.shared::cta.global.mbarrier::complete_tx::bytes [%0], [%1], %2, [%3];"
                 :: "r"(dst), "l"(src), "r"(bytes), "r"(mbar) : "memory");
}
__device__ __forceinline__ void mbar_wait(uint32_t a, uint32_t parity) {
    uint32_t done;
    asm volatile(
        "{\n\t.reg .pred p;\n\t"
        "mbarrier.try_wait.parity.acquire.cta.shared::cta.b64 p, [%1], %2;\n\t"
        "selp.b32 %0, 1, 0, p;\n\t}"
        : "=r"(done) : "r"(a), "r"(parity) : "memory");
    while (!done) {
        asm volatile(
            "{\n\t.reg .pred p;\n\t"
            "mbarrier.try_wait.parity.acquire.cta.shared::cta.b64 p, [%1], %2, 0x989680;\n\t"
            "selp.b32 %0, 1, 0, p;\n\t}"
            : "=r"(done) : "r"(a), "r"(parity) : "memory");
    }
}
__device__ __forceinline__ void prefetch_l2(const void* p) {
    asm volatile("prefetch.global.L2 [%0];" :: "l"(p));
}

// Prefetch one 36864B chunk into L2: 288 lines of 128B, 256 threads.
__device__ __forceinline__ void prefetch_chunk(const float* base, int t) {
    prefetch_l2(base + t * 32);
    if (t < 32) prefetch_l2(base + (t + 256) * 32);
}

__global__ void __launch_bounds__(NT, 3)
xonv2d_kernel(const float* __restrict__ x,
              const float* __restrict__ wts,
              const float* __restrict__ bias,
              float* __restrict__ out)
{
    extern __shared__ char smem[];
    float*   swt  = reinterpret_cast<float*>(smem);
    __half*  sxh  = reinterpret_cast<__half*>(smem + SMEM_X_OFF);
    float*   sof  = reinterpret_cast<float*>(smem + SMEM_X_OFF);   // epilogue overlay
    float4*  sof4 = reinterpret_cast<float4*>(smem + SMEM_X_OFF);
    const uint2* sxu2 = reinterpret_cast<const uint2*>(smem + SMEM_X_OFF);
    const uint32_t mb = smem_u32(smem + SMEM_MBAR_OFF);

    const int t   = threadIdx.x;
    const int bid = blockIdx.x;

    if (t == 0) { mbar_init(mb, 1); mbar_init(mb + 8, 1); }
    __syncthreads();

    // Prologue: TMA chunks bid, bid+GRID; prefetch chunks bid+2G, bid+3G.
    if (t == 0) {
        mbar_expect_tx(mb, CHUNK_BYTES);
        tma_bulk_g2s(smem_u32(swt), wts + (size_t)bid * CHUNK_FLOATS, CHUNK_BYTES, mb);
        mbar_expect_tx(mb + 8, CHUNK_BYTES);
        tma_bulk_g2s(smem_u32(swt + CHUNK_FLOATS),
                     wts + (size_t)(bid + GRID) * CHUNK_FLOATS, CHUNK_BYTES, mb + 8);
    }
    #pragma unroll
    for (int pj = 2; pj < PF_DIST; pj++) {
        const int gp = bid + pj * GRID;
        if (gp < GROUPS) prefetch_chunk(wts + (size_t)gp * CHUNK_FLOATS, t);
    }

    // Lane mapping: o0l=bit0, ch=bits1-3 (cin pair), o0h=bit4; warp: o0m=bit5, px=bits6-7.
    const int o0  = (t & 1) + 2 * ((t >> 4) & 1) + 4 * ((t >> 5) & 1);
    const int ch  = (t >> 1) & 7;
    const int px  = (t >> 6) & 3;
    const int xsw = (ch >> 1) & 3;
    const int wbase_f2 = px * (FLOATS_PER_PX / 2) + o0 * 72 + ch * 9;
    const int xb0 = (2 * ch) * 18 + px;
    const int xb1 = xb0 + 18;

    // Precomputed x-fill constants (loop-invariant).
    int goff[5], sidx[5], pk[5];
    #pragma unroll
    for (int it = 0; it < 5; it++) {
        const int i = t + it * NT;
        if (i < XTILE) {
            const int wi = i % 6;
            const int r  = (i / 6) % 3;
            const int c  = (i / 18) % 16;
            const int b  = i / 288;
            goff[it] = ((b * 16 + c) * Hc + (r - 1)) * Wc + (wi - 1);
            sidx[it] = ((c * 18 + r * 6 + wi) ^ ((c >> 2) & 3)) * 4 + b;
            pk[it]   = r | (wi << 4);
        }
    }

    // x prefetch for first chunk.
    float xr[5];
    {
        const int p0 = bid * 4;
        const int h0 = p0 >> 7, w0 = p0 & 127;
        #pragma unroll
        for (int it = 0; it < 5; it++) {
            const int i = t + it * NT;
            if (i < XTILE) {
                const int hh = h0 + (pk[it] & 15) - 1;
                const int ww = w0 + (pk[it] >> 4) - 1;
                xr[it] = ((unsigned)hh < 128u && (unsigned)ww < 128u)
                         ? __ldg(x + goff[it] + p0) : 0.0f;
            }
        }
    }
    // bias prefetch for first chunk.
    float bs0 = 0.f, bs1 = 0.f, bs2 = 0.f, bs3 = 0.f;
    if (t < 64) {
        const float* bp = bias + (size_t)bid * 64 + (t & 15);
        bs0 = __ldg(bp); bs1 = __ldg(bp + 16); bs2 = __ldg(bp + 32); bs3 = __ldg(bp + 48);
    }

    for (int j = 0, gi = bid; gi < GROUPS; j++, gi += GRID) {
        const int slot   = j & 1;
        const int parity = (j >> 1) & 1;

        __syncthreads();   // S1: prev epilogue reads done -> x tile writable

        // Store prefetched x (fp16) into the tile.
        #pragma unroll
        for (int it = 0; it < 5; it++) {
            const int i = t + it * NT;
            if (i < XTILE) sxh[sidx[it]] = __float2half_rn(xr[it]);
        }
        __syncthreads();   // S2: x tile ready

        // L2 prefetch for chunk j+PF_DIST (keeps DRAM queues full, deep MLP).
        {
            const int gp = gi + PF_DIST * GRID;
            if (gp < GROUPS) prefetch_chunk(wts + (size_t)gp * CHUNK_FLOATS, t);
        }

        // Prefetch x + bias for next chunk (hidden behind mbar_wait + compute).
        float bn0 = 0.f, bn1 = 0.f, bn2 = 0.f, bn3 = 0.f;
        {
            const int gn1 = gi + GRID;
            if (gn1 < GROUPS) {
                const int p1 = gn1 * 4;
                const int h0 = p1 >> 7, w0 = p1 & 127;
                #pragma unroll
                for (int it = 0; it < 5; it++) {
                    const int i = t + it * NT;
                    if (i < XTILE) {
                        const int hh = h0 + (pk[it] & 15) - 1;
                        const int ww = w0 + (pk[it] >> 4) - 1;
                        xr[it] = ((unsigned)hh < 128u && (unsigned)ww < 128u)
                                 ? __ldg(x + goff[it] + p1) : 0.0f;
                    }
                }
                if (t < 64) {
                    const float* bp = bias + (size_t)gn1 * 64 + (t & 15);
                    bn0 = __ldg(bp); bn1 = __ldg(bp + 16);
                    bn2 = __ldg(bp + 32); bn3 = __ldg(bp + 48);
                }
            }
        }

        mbar_wait(mb + slot * 8, parity);  // weights for chunk gi ready

        const float2* wp = reinterpret_cast<const float2*>(swt + slot * CHUNK_FLOATS) + wbase_f2;

        float a00 = 0.f, a01 = 0.f, a02 = 0.f, a03 = 0.f;
        float a10 = 0.f, a11 = 0.f, a12 = 0.f, a13 = 0.f;

        #pragma unroll
        for (int k = 0; k < 9; k++) {
            const float2 w0v = wp[k];          // cout o0
            const float2 w1v = wp[k + 576];    // cout o0+8
            #pragma unroll
            for (int e = 0; e < 2; e++) {
                const int f   = 2 * k + e;     // 0..17
                const int cc  = f / 9;
                const int tap = f % 9;
                const int r   = tap / 3;
                const int s   = tap % 3;
                const int W   = ((cc ? xb1 : xb0) + r * 6 + s) ^ xsw;
                union { uint2 u; __half2 h[2]; } raw;
                raw.u = sxu2[W];
                const float2 lo = __half22float2(raw.h[0]);
                const float2 hi = __half22float2(raw.h[1]);
                const float wa = e ? w0v.y : w0v.x;
                const float wb = e ? w1v.y : w1v.x;
                a00 += wa * lo.x;  a01 += wa * lo.y;  a02 += wa * hi.x;  a03 += wa * hi.y;
                a10 += wb * lo.x;  a11 += wb * lo.y;  a12 += wb * hi.x;  a13 += wb * hi.y;
            }
        }

        // Reduce over ch (lane bits 1-3): 3 butterflies.
        #pragma unroll
        for (int m = 2; m <= 8; m <<= 1) {
            a00 += __shfl_xor_sync(0xffffffffu, a00, m);
            a01 += __shfl_xor_sync(0xffffffffu, a01, m);
            a02 += __shfl_xor_sync(0xffffffffu, a02, m);
            a03 += __shfl_xor_sync(0xffffffffu, a03, m);
            a10 += __shfl_xor_sync(0xffffffffu, a10, m);
            a11 += __shfl_xor_sync(0xffffffffu, a11, m);
            a12 += __shfl_xor_sync(0xffffffffu, a12, m);
            a13 += __shfl_xor_sync(0xffffffffu, a13, m);
        }

        __syncthreads();   // S3: all x-tile + weight-slot reads done

        // Weight TMA for chunk j+2 into this (now free) slot -> should hit L2.
        if (t == 0) {
            const int gn = gi + 2 * GRID;
            if (gn < GROUPS) {
                mbar_expect_tx(mb + slot * 8, CHUNK_BYTES);
                tma_bulk_g2s(smem_u32(swt + slot * CHUNK_FLOATS),
                             wts + (size_t)gn * CHUNK_FLOATS, CHUNK_BYTES, mb + slot * 8);
            }
        }

        // Stage outputs (fp32, overlaid on the x tile): sout[(b*16+o)*4 + px].
        if (ch == 0) {
            const int o1 = o0 + 8;
            sof[(0 * 16 + o0) * 4 + px] = a00;
            sof[(1 * 16 + o0) * 4 + px] = a01;
            sof[(2 * 16 + o0) * 4 + px] = a02;
            sof[(3 * 16 + o0) * 4 + px] = a03;
            sof[(0 * 16 + o1) * 4 + px] = a10;
            sof[(1 * 16 + o1) * 4 + px] = a11;
            sof[(2 * 16 + o1) * 4 + px] = a12;
            sof[(3 * 16 + o1) * 4 + px] = a13;
        }
        __syncthreads();   // S4: sout ready

        // Coalesced write: thread t<64 -> (b = t>>4, o = t&15), float4 over 4 pixels.
        if (t < 64) {
            float4 v = sof4[t];
            v.x += bs0; v.y += bs1; v.z += bs2; v.w += bs3;
            *reinterpret_cast<float4*>(out + (size_t)t * (Hc * Wc) + gi * 4) = v;
            bs0 = bn0; bs1 = bn1; bs2 = bn2; bs3 = bn3;
        }
    }
}

extern "C" void kernel_launch(void* const* d_in, const int* in_sizes, int n_in,
                              void* d_out, int out_size) {
    const float* x    = (const float*)d_in[0];
    const float* wts  = (const float*)d_in[1];
    const float* bias = (const float*)d_in[2];
    float* out        = (float*)d_out;

    cudaFuncSetAttribute(xonv2d_kernel, cudaFuncAttributeMaxDynamicSharedMemorySize, SMEM_TOTAL);
    cudaFuncSetAttribute(xonv2d_kernel, cudaFuncAttributePreferredSharedMemoryCarveout, 100);
    xonv2d_kernel<<<GRID, NT, SMEM_TOTAL>>>(x, wts, bias, out);
}

// round 14
// speedup vs baseline: 1.1665x; 1.1665x over previous
#include <cuda_runtime.h>
#include <cuda_fp16.h>
#include <cstdint>
#include <cstddef>

// Xonv2D: out[b,o,h,w] = sum_{c,kh,kw} x[b,c,h+kh-1,w+kw-1] * W[h,w,o,c,kh,kw] + bias[h,w,o]
// B=4, CIN=COUT=16, K=3, H=W=128. Weights = 151MB streamed once -> HBM-bound.
// Round 14 = R10 (3 CTAs/SM x 256thr, 4px chunks, ring-2 TMA, fp16 x tile) with
// the serial loop body slimmed: padded-stride x layout (19 uint2/c -> 1-phase
// LDS.64, zero swizzle ALU, compile-time offsets) and 2 barriers/iter via a
// dedicated sout buffer. smem 77200B -> still 3 CTAs/SM.

static constexpr int Hc = 128, Wc = 128;
static constexpr int GROUPS = 4096;                      // 4-pixel groups
static constexpr int FLOATS_PER_PX = 16 * 16 * 9;        // 2304
static constexpr int CHUNK_FLOATS  = 4 * FLOATS_PER_PX;  // 9216
static constexpr int CHUNK_BYTES   = CHUNK_FLOATS * 4;   // 36864
static constexpr int CSTR          = 19;                 // uint2 per c (3r*6wi=18 + 1 pad)
static constexpr int XTILE_ELEMS   = 1152;               // real halfs*? (16c*3r*6wi, one uint2 each = 288 uint2)
static constexpr int XTILE_BYTES   = 16 * CSTR * 8;      // 2432
static constexpr int SMEM_X_OFF    = 2 * CHUNK_BYTES;            // 73728
static constexpr int SMEM_OUT_OFF  = SMEM_X_OFF + XTILE_BYTES;   // 76160
static constexpr int SMEM_MBAR_OFF = SMEM_OUT_OFF + 256 * 4;     // 77184
static constexpr int SMEM_TOTAL    = SMEM_MBAR_OFF + 16;         // 77200 (x3 = 231600 <= 233472)
static constexpr int GRID          = 456;                // 3 CTAs/SM * 152 SMs
static constexpr int NT            = 256;

__device__ __forceinline__ uint32_t smem_u32(const void* p) {
    return (uint32_t)__cvta_generic_to_shared(p);
}
__device__ __forceinline__ void mbar_init(uint32_t a, uint32_t count) {
    asm volatile("mbarrier.init.shared.b64 [%0], %1;" :: "r"(a), "r"(count) : "memory");
}
__device__ __forceinline__ void mbar_expect_tx(uint32_t a, uint32_t bytes) {
    asm volatile("mbarrier.arrive.expect_tx.shared.b64 _, [%0], %1;" :: "r"(a), "r"(bytes) : "memory");
}
__device__ __forceinline__ void tma_bulk_g2s(uint32_t dst, const void* src, uint32_t bytes, uint32_t mbar) {
    asm volatile("cp.async.bulk.shared::cta.global.mbarrier::complete_tx::bytes [%0], [%1], %2, [%3];"
                 :: "r"(dst), "l"(src), "r"(bytes), "r"(mbar) : "memory");
}
__device__ __forceinline__ void mbar_wait(uint32_t a, uint32_t parity) {
    uint32_t done;
    asm volatile(
        "{\n\t.reg .pred p;\n\t"
        "mbarrier.try_wait.parity.acquire.cta.shared::cta.b64 p, [%1], %2;\n\t"
        "selp.b32 %0, 1, 0, p;\n\t}"
        : "=r"(done) : "r"(a), "r"(parity) : "memory");
    while (!done) {
        asm volatile(
            "{\n\t.reg .pred p;\n\t"
            "mbarrier.try_wait.parity.acquire.cta.shared::cta.b64 p, [%1], %2, 0x989680;\n\t"
            "selp.b32 %0, 1, 0, p;\n\t}"
            : "=r"(done) : "r"(a), "r"(parity) : "memory");
    }
}

__global__ void __launch_bounds__(NT, 3)
xonv2d_kernel(const float* __restrict__ x,
              const float* __restrict__ wts,
              const float* __restrict__ bias,
              float* __restrict__ out)
{
    extern __shared__ char smem[];
    float*   swt  = reinterpret_cast<float*>(smem);
    __half*  sxh  = reinterpret_cast<__half*>(smem + SMEM_X_OFF);
    const uint2* sxu2 = reinterpret_cast<const uint2*>(smem + SMEM_X_OFF);
    float*   sof  = reinterpret_cast<float*>(smem + SMEM_OUT_OFF);
    float4*  sof4 = reinterpret_cast<float4*>(smem + SMEM_OUT_OFF);
    const uint32_t mb = smem_u32(smem + SMEM_MBAR_OFF);

    const int t   = threadIdx.x;
    const int bid = blockIdx.x;

    if (t == 0) { mbar_init(mb, 1); mbar_init(mb + 8, 1); }
    __syncthreads();

    // Prologue: weight TMA for chunks bid (slot0), bid+GRID (slot1).
    if (t == 0) {
        mbar_expect_tx(mb, CHUNK_BYTES);
        tma_bulk_g2s(smem_u32(swt), wts + (size_t)bid * CHUNK_FLOATS, CHUNK_BYTES, mb);
        mbar_expect_tx(mb + 8, CHUNK_BYTES);
        tma_bulk_g2s(smem_u32(swt + CHUNK_FLOATS),
                     wts + (size_t)(bid + GRID) * CHUNK_FLOATS, CHUNK_BYTES, mb + 8);
    }

    // Lane mapping: o0l=bit0, ch=bits1-3 (cin pair), o0h=bit4; warp: o0m=bit5, px=bits6-7.
    const int o0  = (t & 1) + 2 * ((t >> 4) & 1) + 4 * ((t >> 5) & 1);
    const int ch  = (t >> 1) & 7;
    const int px  = (t >> 6) & 3;
    const int wbase_f2 = px * (FLOATS_PER_PX / 2) + o0 * 72 + ch * 9;
    const int xb = 2 * ch * CSTR + px;   // uint2 index; + cc*CSTR + r*6 + s (all immediates)

    // Precomputed x-fill constants (loop-invariant). 1152 elements, 5 rounds of 256.
    int goff[5], sidx[5], pk[5];
    #pragma unroll
    for (int it = 0; it < 5; it++) {
        const int i = t + it * NT;
        if (i < XTILE_ELEMS) {
            const int wi = i % 6;
            const int r  = (i / 6) % 3;
            const int c  = (i / 18) % 16;
            const int b  = i / 288;
            goff[it] = ((b * 16 + c) * Hc + (r - 1)) * Wc + (wi - 1);
            sidx[it] = (c * CSTR + r * 6 + wi) * 4 + b;   // half index, padded stride
            pk[it]   = r | (wi << 4);
        }
    }

    // x prefetch for first chunk.
    float xr[5];
    {
        const int p0 = bid * 4;
        const int h0 = p0 >> 7, w0 = p0 & 127;
        #pragma unroll
        for (int it = 0; it < 5; it++) {
            const int i = t + it * NT;
            if (i < XTILE_ELEMS) {
                const int hh = h0 + (pk[it] & 15) - 1;
                const int ww = w0 + (pk[it] >> 4) - 1;
                xr[it] = ((unsigned)hh < 128u && (unsigned)ww < 128u)
                         ? __ldg(x + goff[it] + p0) : 0.0f;
            }
        }
    }
    // bias prefetch for first chunk.
    float bs0 = 0.f, bs1 = 0.f, bs2 = 0.f, bs3 = 0.f;
    if (t < 64) {
        const float* bp = bias + (size_t)bid * 64 + (t & 15);
        bs0 = __ldg(bp); bs1 = __ldg(bp + 16); bs2 = __ldg(bp + 32); bs3 = __ldg(bp + 48);
    }

    for (int j = 0, gi = bid; gi < GROUPS; j++, gi += GRID) {
        const int slot   = j & 1;
        const int parity = (j >> 1) & 1;

        // STS x (fp16). Safe: S4(j-1) ordered all compute(j-1) x reads before this.
        #pragma unroll
        for (int it = 0; it < 5; it++) {
            const int i = t + it * NT;
            if (i < XTILE_ELEMS) sxh[sidx[it]] = __float2half_rn(xr[it]);
        }

        // Prefetch x + bias for next chunk (LDGs issued before the barrier).
        float bn0 = 0.f, bn1 = 0.f, bn2 = 0.f, bn3 = 0.f;
        {
            const int gn1 = gi + GRID;
            if (gn1 < GROUPS) {
                const int p1 = gn1 * 4;
                const int h0 = p1 >> 7, w0 = p1 & 127;
                #pragma unroll
                for (int it = 0; it < 5; it++) {
                    const int i = t + it * NT;
                    if (i < XTILE_ELEMS) {
                        const int hh = h0 + (pk[it] & 15) - 1;
                        const int ww = w0 + (pk[it] >> 4) - 1;
                        xr[it] = ((unsigned)hh < 128u && (unsigned)ww < 128u)
                                 ? __ldg(x + goff[it] + p1) : 0.0f;
                    }
                }
                if (t < 64) {
                    const float* bp = bias + (size_t)gn1 * 64 + (t & 15);
                    bn0 = __ldg(bp); bn1 = __ldg(bp + 16);
                    bn2 = __ldg(bp + 32); bn3 = __ldg(bp + 48);
                }
            }
        }

        __syncthreads();   // S2: x tile ready; prev STG sout reads done

        mbar_wait(mb + slot * 8, parity);  // weights for chunk gi ready

        const float2* wp = reinterpret_cast<const float2*>(swt + slot * CHUNK_FLOATS) + wbase_f2;
        const uint2*  xp = sxu2 + xb;

        float a00 = 0.f, a01 = 0.f, a02 = 0.f, a03 = 0.f;
        float a10 = 0.f, a11 = 0.f, a12 = 0.f, a13 = 0.f;

        #pragma unroll
        for (int k = 0; k < 9; k++) {
            const float2 w0v = wp[k];          // cout o0
            const float2 w1v = wp[k + 576];    // cout o0+8
            #pragma unroll
            for (int e = 0; e < 2; e++) {
                const int f   = 2 * k + e;     // 0..17
                const int cc  = f / 9;
                const int tap = f % 9;
                const int r   = tap / 3;
                const int s   = tap % 3;
                union { uint2 u; __half2 h[2]; } raw;
                raw.u = xp[cc * CSTR + r * 6 + s];   // compile-time immediate offset
                const float2 lo = __half22float2(raw.h[0]);
                const float2 hi = __half22float2(raw.h[1]);
                const float wa = e ? w0v.y : w0v.x;
                const float wb = e ? w1v.y : w1v.x;
                a00 += wa * lo.x;  a01 += wa * lo.y;  a02 += wa * hi.x;  a03 += wa * hi.y;
                a10 += wb * lo.x;  a11 += wb * lo.y;  a12 += wb * hi.x;  a13 += wb * hi.y;
            }
        }

        // Reduce over ch (lane bits 1-3): 3 butterflies.
        #pragma unroll
        for (int m = 2; m <= 8; m <<= 1) {
            a00 += __shfl_xor_sync(0xffffffffu, a00, m);
            a01 += __shfl_xor_sync(0xffffffffu, a01, m);
            a02 += __shfl_xor_sync(0xffffffffu, a02, m);
            a03 += __shfl_xor_sync(0xffffffffu, a03, m);
            a10 += __shfl_xor_sync(0xffffffffu, a10, m);
            a11 += __shfl_xor_sync(0xffffffffu, a11, m);
            a12 += __shfl_xor_sync(0xffffffffu, a12, m);
            a13 += __shfl_xor_sync(0xffffffffu, a13, m);
        }

        // Stage outputs into the dedicated sout buffer.
        if (ch == 0) {
            const int o1 = o0 + 8;
            sof[(0 * 16 + o0) * 4 + px] = a00;
            sof[(1 * 16 + o0) * 4 + px] = a01;
            sof[(2 * 16 + o0) * 4 + px] = a02;
            sof[(3 * 16 + o0) * 4 + px] = a03;
            sof[(0 * 16 + o1) * 4 + px] = a10;
            sof[(1 * 16 + o1) * 4 + px] = a11;
            sof[(2 * 16 + o1) * 4 + px] = a12;
            sof[(3 * 16 + o1) * 4 + px] = a13;
        }
        __syncthreads();   // S4: sout ready; all x-tile + weight-slot reads of chunk j done

        // Weight TMA for chunk j+2 into this (now free) slot.
        if (t == 0) {
            const int gn = gi + 2 * GRID;
            if (gn < GROUPS) {
                mbar_expect_tx(mb + slot * 8, CHUNK_BYTES);
                tma_bulk_g2s(smem_u32(swt + slot * CHUNK_FLOATS),
                             wts + (size_t)gn * CHUNK_FLOATS, CHUNK_BYTES, mb + slot * 8);
            }
        }

        // Coalesced write: thread t<64 -> (b = t>>4, o = t&15), float4 over 4 pixels.
        if (t < 64) {
            float4 v = sof4[t];
            v.x += bs0; v.y += bs1; v.z += bs2; v.w += bs3;
            *reinterpret_cast<float4*>(out + (size_t)t * (Hc * Wc) + gi * 4) = v;
            bs0 = bn0; bs1 = bn1; bs2 = bn2; bs3 = bn3;
        }
    }
}

extern "C" void kernel_launch(void* const* d_in, const int* in_sizes, int n_in,
                              void* d_out, int out_size) {
    const float* x    = (const float*)d_in[0];
    const float* wts  = (const float*)d_in[1];
    const float* bias = (const float*)d_in[2];
    float* out        = (float*)d_out;

    cudaFuncSetAttribute(xonv2d_kernel, cudaFuncAttributeMaxDynamicSharedMemorySize, SMEM_TOTAL);
    xonv2d_kernel<<<GRID, NT, SMEM_TOTAL>>>(x, wts, bias, out);
}

// round 15
// speedup vs baseline: 1.1803x; 1.0118x over previous
#include <cuda_runtime.h>
#include <cuda_fp16.h>
#include <cstdint>
#include <cstddef>

// Xonv2D: out[b,o,h,w] = sum_{c,kh,kw} x[b,c,h+kh-1,w+kw-1] * W[h,w,o,c,kh,kw] + bias[h,w,o]
// B=4, CIN=COUT=16, K=3, H=W=128. Weights = 151MB streamed once -> HBM-bound.
// Round 15 = Round 14 (3 CTAs/SM x 256thr, ring-2 TMA, fp16 padded-stride x
// tile, 2 barriers/iter) with the FMA block vectorized via fma.rn.f32x2:
// 144 FFMA -> 72 FFMA2 (batch-paired accumulators), ~15% fewer issue slots.

static constexpr int Hc = 128, Wc = 128;
static constexpr int GROUPS = 4096;                      // 4-pixel groups
static constexpr int FLOATS_PER_PX = 16 * 16 * 9;        // 2304
static constexpr int CHUNK_FLOATS  = 4 * FLOATS_PER_PX;  // 9216
static constexpr int CHUNK_BYTES   = CHUNK_FLOATS * 4;   // 36864
static constexpr int CSTR          = 19;                 // uint2 per c (18 + 1 pad)
static constexpr int XTILE_ELEMS   = 1152;
static constexpr int XTILE_BYTES   = 16 * CSTR * 8;      // 2432
static constexpr int SMEM_X_OFF    = 2 * CHUNK_BYTES;            // 73728
static constexpr int SMEM_OUT_OFF  = SMEM_X_OFF + XTILE_BYTES;   // 76160
static constexpr int SMEM_MBAR_OFF = SMEM_OUT_OFF + 256 * 4;     // 77184
static constexpr int SMEM_TOTAL    = SMEM_MBAR_OFF + 16;         // 77200 (x3 <= 233472)
static constexpr int GRID          = 456;                // 3 CTAs/SM * 152 SMs
static constexpr int NT            = 256;

__device__ __forceinline__ uint32_t smem_u32(const void* p) {
    return (uint32_t)__cvta_generic_to_shared(p);
}
__device__ __forceinline__ void mbar_init(uint32_t a, uint32_t count) {
    asm volatile("mbarrier.init.shared.b64 [%0], %1;" :: "r"(a), "r"(count) : "memory");
}
__device__ __forceinline__ void mbar_expect_tx(uint32_t a, uint32_t bytes) {
    asm volatile("mbarrier.arrive.expect_tx.shared.b64 _, [%0], %1;" :: "r"(a), "r"(bytes) : "memory");
}
__device__ __forceinline__ void tma_bulk_g2s(uint32_t dst, const void* src, uint32_t bytes, uint32_t mbar) {
    asm volatile("cp.async.bulk.shared::cta.global.mbarrier::complete_tx::bytes [%0], [%1], %2, [%3];"
                 :: "r"(dst), "l"(src), "r"(bytes), "r"(mbar) : "memory");
}
__device__ __forceinline__ void mbar_wait(uint32_t a, uint32_t parity) {
    uint32_t done;
    asm volatile(
        "{\n\t.reg .pred p;\n\t"
        "mbarrier.try_wait.parity.acquire.cta.shared::cta.b64 p, [%1], %2;\n\t"
        "selp.b32 %0, 1, 0, p;\n\t}"
        : "=r"(done) : "r"(a), "r"(parity) : "memory");
    while (!done) {
        asm volatile(
            "{\n\t.reg .pred p;\n\t"
            "mbarrier.try_wait.parity.acquire.cta.shared::cta.b64 p, [%1], %2, 0x989680;\n\t"
            "selp.b32 %0, 1, 0, p;\n\t}"
            : "=r"(done) : "r"(a), "r"(parity) : "memory");
    }
}

// f32x2 helpers
__device__ __forceinline__ unsigned long long f32x2_pack(float lo, float hi) {
    unsigned long long r;
    asm("mov.b64 %0, {%1, %2};" : "=l"(r) : "f"(lo), "f"(hi));
    return r;
}
__device__ __forceinline__ unsigned long long f32x2_dup(float v) {
    unsigned long long r;
    asm("mov.b64 %0, {%1, %1};" : "=l"(r) : "f"(v));
    return r;
}
__device__ __forceinline__ void ffma2(unsigned long long& acc, unsigned long long a, unsigned long long b) {
    asm("fma.rn.f32x2 %0, %1, %2, %0;" : "+l"(acc) : "l"(a), "l"(b));
}
__device__ __forceinline__ float2 f32x2_unpack(unsigned long long v) {
    float2 r;
    asm("mov.b64 {%0, %1}, %2;" : "=f"(r.x), "=f"(r.y) : "l"(v));
    return r;
}

__global__ void __launch_bounds__(NT, 3)
xonv2d_kernel(const float* __restrict__ x,
              const float* __restrict__ wts,
              const float* __restrict__ bias,
              float* __restrict__ out)
{
    extern __shared__ char smem[];
    float*   swt  = reinterpret_cast<float*>(smem);
    __half*  sxh  = reinterpret_cast<__half*>(smem + SMEM_X_OFF);
    const uint2* sxu2 = reinterpret_cast<const uint2*>(smem + SMEM_X_OFF);
    float*   sof  = reinterpret_cast<float*>(smem + SMEM_OUT_OFF);
    float4*  sof4 = reinterpret_cast<float4*>(smem + SMEM_OUT_OFF);
    const uint32_t mb = smem_u32(smem + SMEM_MBAR_OFF);

    const int t   = threadIdx.x;
    const int bid = blockIdx.x;

    if (t == 0) { mbar_init(mb, 1); mbar_init(mb + 8, 1); }
    __syncthreads();

    // Prologue: weight TMA for chunks bid (slot0), bid+GRID (slot1).
    if (t == 0) {
        mbar_expect_tx(mb, CHUNK_BYTES);
        tma_bulk_g2s(smem_u32(swt), wts + (size_t)bid * CHUNK_FLOATS, CHUNK_BYTES, mb);
        mbar_expect_tx(mb + 8, CHUNK_BYTES);
        tma_bulk_g2s(smem_u32(swt + CHUNK_FLOATS),
                     wts + (size_t)(bid + GRID) * CHUNK_FLOATS, CHUNK_BYTES, mb + 8);
    }

    // Lane mapping: o0l=bit0, ch=bits1-3 (cin pair), o0h=bit4; warp: o0m=bit5, px=bits6-7.
    const int o0  = (t & 1) + 2 * ((t >> 4) & 1) + 4 * ((t >> 5) & 1);
    const int ch  = (t >> 1) & 7;
    const int px  = (t >> 6) & 3;
    const int wbase_f2 = px * (FLOATS_PER_PX / 2) + o0 * 72 + ch * 9;
    const int xb = 2 * ch * CSTR + px;   // uint2 index; + cc*CSTR + r*6 + s (immediates)

    // Precomputed x-fill constants (loop-invariant). 1152 elements, 5 rounds of 256.
    int goff[5], sidx[5], pk[5];
    #pragma unroll
    for (int it = 0; it < 5; it++) {
        const int i = t + it * NT;
        if (i < XTILE_ELEMS) {
            const int wi = i % 6;
            const int r  = (i / 6) % 3;
            const int c  = (i / 18) % 16;
            const int b  = i / 288;
            goff[it] = ((b * 16 + c) * Hc + (r - 1)) * Wc + (wi - 1);
            sidx[it] = (c * CSTR + r * 6 + wi) * 4 + b;
            pk[it]   = r | (wi << 4);
        }
    }

    // x prefetch for first chunk.
    float xr[5];
    {
        const int p0 = bid * 4;
        const int h0 = p0 >> 7, w0 = p0 & 127;
        #pragma unroll
        for (int it = 0; it < 5; it++) {
            const int i = t + it * NT;
            if (i < XTILE_ELEMS) {
                const int hh = h0 + (pk[it] & 15) - 1;
                const int ww = w0 + (pk[it] >> 4) - 1;
                xr[it] = ((unsigned)hh < 128u && (unsigned)ww < 128u)
                         ? __ldg(x + goff[it] + p0) : 0.0f;
            }
        }
    }
    // bias prefetch for first chunk.
    float bs0 = 0.f, bs1 = 0.f, bs2 = 0.f, bs3 = 0.f;
    if (t < 64) {
        const float* bp = bias + (size_t)bid * 64 + (t & 15);
        bs0 = __ldg(bp); bs1 = __ldg(bp + 16); bs2 = __ldg(bp + 32); bs3 = __ldg(bp + 48);
    }

    for (int j = 0, gi = bid; gi < GROUPS; j++, gi += GRID) {
        const int slot   = j & 1;
        const int parity = (j >> 1) & 1;

        // STS x (fp16). Safe: S4(j-1) ordered all compute(j-1) x reads before this.
        #pragma unroll
        for (int it = 0; it < 5; it++) {
            const int i = t + it * NT;
            if (i < XTILE_ELEMS) sxh[sidx[it]] = __float2half_rn(xr[it]);
        }

        // Prefetch x + bias for next chunk (LDGs issued before the barrier).
        float bn0 = 0.f, bn1 = 0.f, bn2 = 0.f, bn3 = 0.f;
        {
            const int gn1 = gi + GRID;
            if (gn1 < GROUPS) {
                const int p1 = gn1 * 4;
                const int h0 = p1 >> 7, w0 = p1 & 127;
                #pragma unroll
                for (int it = 0; it < 5; it++) {
                    const int i = t + it * NT;
                    if (i < XTILE_ELEMS) {
                        const int hh = h0 + (pk[it] & 15) - 1;
                        const int ww = w0 + (pk[it] >> 4) - 1;
                        xr[it] = ((unsigned)hh < 128u && (unsigned)ww < 128u)
                                 ? __ldg(x + goff[it] + p1) : 0.0f;
                    }
                }
                if (t < 64) {
                    const float* bp = bias + (size_t)gn1 * 64 + (t & 15);
                    bn0 = __ldg(bp); bn1 = __ldg(bp + 16);
                    bn2 = __ldg(bp + 32); bn3 = __ldg(bp + 48);
                }
            }
        }

        __syncthreads();   // S2: x tile ready; prev STG sout reads done

        mbar_wait(mb + slot * 8, parity);  // weights for chunk gi ready

        const float2* wp = reinterpret_cast<const float2*>(swt + slot * CHUNK_FLOATS) + wbase_f2;
        const uint2*  xp = sxu2 + xb;

        // Packed accumulators: (b0,b1) and (b2,b3) pairs for couts o0 and o0+8.
        unsigned long long c0lo = 0ull, c0hi = 0ull, c1lo = 0ull, c1hi = 0ull;

        #pragma unroll
        for (int k = 0; k < 9; k++) {
            const float2 w0v = wp[k];          // cout o0   (taps f=2k, 2k+1)
            const float2 w1v = wp[k + 576];    // cout o0+8
            #pragma unroll
            for (int e = 0; e < 2; e++) {
                const int f   = 2 * k + e;     // 0..17
                const int cc  = f / 9;
                const int tap = f % 9;
                const int r   = tap / 3;
                const int s   = tap % 3;
                union { uint2 u; __half2 h[2]; } raw;
                raw.u = xp[cc * CSTR + r * 6 + s];   // compile-time immediate offset
                const float2 lo = __half22float2(raw.h[0]);
                const float2 hi = __half22float2(raw.h[1]);
                const unsigned long long xlo = f32x2_pack(lo.x, lo.y);
                const unsigned long long xhi = f32x2_pack(hi.x, hi.y);
                const unsigned long long wa2 = f32x2_dup(e ? w0v.y : w0v.x);
                const unsigned long long wb2 = f32x2_dup(e ? w1v.y : w1v.x);
                ffma2(c0lo, wa2, xlo);
                ffma2(c0hi, wa2, xhi);
                ffma2(c1lo, wb2, xlo);
                ffma2(c1hi, wb2, xhi);
            }
        }

        const float2 u0 = f32x2_unpack(c0lo);
        const float2 u1 = f32x2_unpack(c0hi);
        const float2 u2 = f32x2_unpack(c1lo);
        const float2 u3 = f32x2_unpack(c1hi);
        float a00 = u0.x, a01 = u0.y, a02 = u1.x, a03 = u1.y;
        float a10 = u2.x, a11 = u2.y, a12 = u3.x, a13 = u3.y;

        // Reduce over ch (lane bits 1-3): 3 butterflies.
        #pragma unroll
        for (int m = 2; m <= 8; m <<= 1) {
            a00 += __shfl_xor_sync(0xffffffffu, a00, m);
            a01 += __shfl_xor_sync(0xffffffffu, a01, m);
            a02 += __shfl_xor_sync(0xffffffffu, a02, m);
            a03 += __shfl_xor_sync(0xffffffffu, a03, m);
            a10 += __shfl_xor_sync(0xffffffffu, a10, m);
            a11 += __shfl_xor_sync(0xffffffffu, a11, m);
            a12 += __shfl_xor_sync(0xffffffffu, a12, m);
            a13 += __shfl_xor_sync(0xffffffffu, a13, m);
        }

        // Stage outputs into the dedicated sout buffer.
        if (ch == 0) {
            const int o1 = o0 + 8;
            sof[(0 * 16 + o0) * 4 + px] = a00;
            sof[(1 * 16 + o0) * 4 + px] = a01;
            sof[(2 * 16 + o0) * 4 + px] = a02;
            sof[(3 * 16 + o0) * 4 + px] = a03;
            sof[(0 * 16 + o1) * 4 + px] = a10;
            sof[(1 * 16 + o1) * 4 + px] = a11;
            sof[(2 * 16 + o1) * 4 + px] = a12;
            sof[(3 * 16 + o1) * 4 + px] = a13;
        }
        __syncthreads();   // S4: sout ready; all x-tile + weight-slot reads of chunk j done

        // Weight TMA for chunk j+2 into this (now free) slot.
        if (t == 0) {
            const int gn = gi + 2 * GRID;
            if (gn < GROUPS) {
                mbar_expect_tx(mb + slot * 8, CHUNK_BYTES);
                tma_bulk_g2s(smem_u32(swt + slot * CHUNK_FLOATS),
                             wts + (size_t)gn * CHUNK_FLOATS, CHUNK_BYTES, mb + slot * 8);
            }
        }

        // Coalesced write: thread t<64 -> (b = t>>4, o = t&15), float4 over 4 pixels.
        if (t < 64) {
            float4 v = sof4[t];
            v.x += bs0; v.y += bs1; v.z += bs2; v.w += bs3;
            *reinterpret_cast<float4*>(out + (size_t)t * (Hc * Wc) + gi * 4) = v;
            bs0 = bn0; bs1 = bn1; bs2 = bn2; bs3 = bn3;
        }
    }
}

extern "C" void kernel_launch(void* const* d_in, const int* in_sizes, int n_in,
                              void* d_out, int out_size) {
    const float* x    = (const float*)d_in[0];
    const float* wts  = (const float*)d_in[1];
    const float* bias = (const float*)d_in[2];
    float* out        = (float*)d_out;

    cudaFuncSetAttribute(xonv2d_kernel, cudaFuncAttributeMaxDynamicSharedMemorySize, SMEM_TOTAL);
    xonv2d_kernel<<<GRID, NT, SMEM_TOTAL>>>(x, wts, bias, out);
}